// round 12
// baseline (speedup 1.0000x reference)
#include <cuda_runtime.h>
#include <cstdint>

// OneDilate: out = 10x10 depthwise box filter of (1-x)*0.5, replicate pad 4.
// x: [32,3,512,512] f32 -> out: [32,3,511,511] f32.
// out = 50 - 0.5 * (sum of 100 raw taps).
//
// R11 skeleton (vertical register-ring + prefetch double-buffer, 1 barrier
// per chunk) + aligned 8-output consume:
//  - produce writes V row shifted by dp=4-a so that consume LDS.128 at the
//    uniform word 4+8*hl is 16B-aligned AND output groups are 16B-aligned
//    in gmem -> 2x STG.128 per thread (4 store wavefronts/row vs 16).
//  - even/odd lanes cover a row pair; VSTR=148 (=4 mod 8) makes the paired
//    LDS.128 pattern cover all 32 banks (conflict-free).
//  - left edge (<=3 cols) via sliding-subtract on lane hl==0; hl==15 and
//    image-edge tiles fall back to predicated scalar stores.

#define IN_H   512
#define IN_W   512
#define OUT_H  511
#define OUT_W  511
#define PLANES 96
#define TILE_X 128
#define TILE_Y 128
#define CH     16
#define NCHUNK 8           // TILE_Y / CH
#define VW     137         // TILE_X + 9 vertical columns
#define VSTR   148         // row stride: %4==0 (16B align), %8==4 (banks)
#define NT     160         // 5 warps

#define OUTV(S) fmaf((S), -0.5f, 50.0f)

// One pipeline step: produce V rows for chunk CK (register history CUR,
// prefetch CK+1 into NXT), single barrier, consume chunk CK from VB.
#define STEP(CK, CUR, NXT, VB) do {                                          \
    const int jb = ty0 + (CK) * CH;                                          \
    if (vrole) {                                                             \
        _Pragma("unroll")                                                    \
        for (int jj = 0; jj < CH; jj++) {                                    \
            float v = CUR[jj];                                               \
            vs += v;                               /* rows [oy-4 .. oy+5] */ \
            int dd = (p + 3 * (jb + jj)) & 3;                                \
            int dp = ((dd - 1) & 3) + 1;           /* 4 - a */               \
            VB[jj * VSTR + dp + t] = vs;           /* vidx c at word c+dp */ \
            vs -= (jj <= 8) ? NXT[jj + 7] : CUR[jj - 9];                     \
        }                                                                    \
        if ((CK) < NCHUNK - 1) {                                             \
            _Pragma("unroll")                                                \
            for (int jj = 0; jj < CH; jj++) {                                \
                int g = jb + CH + jj + 5;                                    \
                g = (g > IN_H - 1) ? IN_H - 1 : g;                           \
                NXT[jj] = xc[g * IN_W];                                      \
            }                                                                \
        }                                                                    \
    }                                                                        \
    __syncthreads();                                                         \
    for (int pr = wrp; pr < CH / 2; pr += 5) {                               \
        const int jj = 2 * pr + erow;                                        \
        const int oy = jb + jj;                                              \
        if (oy < OUT_H) {                                                    \
            const int dd = (p + 3 * oy) & 3;                                 \
            const int a  = (4 - dd) & 3;                                     \
            const float* __restrict__ row = VB + jj * VSTR;                  \
            const float4* __restrict__ qp = (const float4*)(row + 4 + 8*hl); \
            float4 q0 = qp[0], q1 = qp[1], q2 = qp[2], q3 = qp[3];           \
            float f16 = qp[4].x;                                             \
            /* f[k] = V col (a + 8*hl + k); output c sums V[c..c+9] */       \
            float s0 = ((q0.x + q0.y) + (q0.z + q0.w))                       \
                     + ((q1.x + q1.y) + (q1.z + q1.w)) + (q2.x + q2.y);      \
            float s1 = s0 - q0.x + q2.z;                                     \
            float s2 = s1 - q0.y + q2.w;                                     \
            float s3 = s2 - q0.z + q3.x;                                     \
            float s4 = s3 - q0.w + q3.y;                                     \
            float s5 = s4 - q1.x + q3.z;                                     \
            float s6 = s5 - q1.y + q3.w;                                     \
            float s7 = s6 - q1.z + f16;                                      \
            float* __restrict__ orow = op + (size_t)oy * OUT_W;              \
            const int ox = tx0 + a + 8 * hl;       /* 16B-aligned */         \
            if (ox + 7 < limG) {                                             \
                *(float4*)(orow + ox) =                                      \
                    make_float4(OUTV(s0), OUTV(s1), OUTV(s2), OUTV(s3));     \
                *(float4*)(orow + ox + 4) =                                  \
                    make_float4(OUTV(s4), OUTV(s5), OUTV(s6), OUTV(s7));     \
            } else {                                                         \
                if (ox     < limG) orow[ox]     = OUTV(s0);                  \
                if (ox + 1 < limG) orow[ox + 1] = OUTV(s1);                  \
                if (ox + 2 < limG) orow[ox + 2] = OUTV(s2);                  \
                if (ox + 3 < limG) orow[ox + 3] = OUTV(s3);                  \
                if (ox + 4 < limG) orow[ox + 4] = OUTV(s4);                  \
                if (ox + 5 < limG) orow[ox + 5] = OUTV(s5);                  \
                if (ox + 6 < limG) orow[ox + 6] = OUTV(s6);                  \
                if (ox + 7 < limG) orow[ox + 7] = OUTV(s7);                  \
            }                                                                \
            if (hl == 0 && a > 0) {                                          \
                /* left edge cols tx0 .. tx0+a-1; words 3,2,1 = V a-1..a-3 */\
                float4 m = *(const float4*)row;                              \
                float qm0 = m.w, qm1 = m.z, qm2 = m.y;                       \
                float f9 = q2.y, f8 = q2.x, f7 = q1.w;                       \
                float sv = s0;                                               \
                sv = sv - f9 + qm0;                 /* col a-1 */            \
                orow[tx0 + a - 1] = OUTV(sv);                                \
                if (a > 1) {                                                 \
                    sv = sv - f8 + qm1;             /* col a-2 */            \
                    orow[tx0 + a - 2] = OUTV(sv);                            \
                }                                                            \
                if (a > 2) {                                                 \
                    sv = sv - f7 + qm2;             /* col a-3 */            \
                    orow[tx0 + a - 3] = OUTV(sv);                            \
                }                                                            \
            }                                                                \
        }                                                                    \
    }                                                                        \
} while (0)

__global__ __launch_bounds__(NT)
void onedilate_kernel(const float* __restrict__ x, float* __restrict__ out)
{
    __shared__ __align__(16) float V[2][CH * VSTR];   // 18,944 B

    const int tx0 = blockIdx.x * TILE_X;
    const int ty0 = blockIdx.y * TILE_Y;
    const int p   = blockIdx.z;
    const float* __restrict__ xp = x   + (size_t)p * IN_H * IN_W;
    float* __restrict__       op = out + (size_t)p * OUT_H * OUT_W;
    const int t = threadIdx.x;

    // vertical role: one input column per thread (clamped = replicate pad)
    int col = tx0 - 4 + t;
    col = (col < 0) ? 0 : (col > IN_W - 1 ? IN_W - 1 : col);
    const float* __restrict__ xc = xp + col;
    const bool vrole = (t < VW);

    // horizontal role: even/odd lanes of warp wrp cover a row pair
    const int lane = t & 31;
    const int wrp  = t >> 5;
    const int erow = lane & 1;
    const int hl   = lane >> 1;                    // 0..15
    const int limG = (tx0 + TILE_X < OUT_W) ? (tx0 + TILE_X) : OUT_W;

    float bufA[CH], bufB[CH];
    float vs = 0.0f;

    if (vrole) {
        // warm-up history: rows ty0-4 .. ty0+4 (clamped) -> bufB[7..15]
        #pragma unroll
        for (int k = 0; k < 9; k++) {
            int g = ty0 - 4 + k;
            g = (g < 0) ? 0 : (g > IN_H - 1 ? IN_H - 1 : g);
            bufB[7 + k] = xc[g * IN_W];
            vs += bufB[7 + k];
        }
        // prefetch chunk 0: rows ty0+5 .. ty0+20 (clamped) -> bufA
        #pragma unroll
        for (int jj = 0; jj < CH; jj++) {
            int g = ty0 + 5 + jj;
            g = (g > IN_H - 1) ? IN_H - 1 : g;
            bufA[jj] = xc[g * IN_W];
        }
    }

    float* __restrict__ V0 = &V[0][0];
    float* __restrict__ V1 = &V[1][0];

    // single barrier per chunk: consume(ck) sits between barrier(ck) and
    // barrier(ck+1); produce(ck+2) into the same buffer is after barrier(ck+1).
    for (int ck = 0; ck < NCHUNK; ck += 2) {
        STEP(ck,     bufA, bufB, V0);
        STEP(ck + 1, bufB, bufA, V1);
    }
}

extern "C" void kernel_launch(void* const* d_in, const int* in_sizes, int n_in,
                              void* d_out, int out_size)
{
    const float* x = (const float*)d_in[0];
    float* out = (float*)d_out;

    dim3 grid((OUT_W + TILE_X - 1) / TILE_X,   // 4
              (OUT_H + TILE_Y - 1) / TILE_Y,   // 4
              PLANES);                          // 96 -> 1536 CTAs (one wave)
    onedilate_kernel<<<grid, NT>>>(x, out);
}